// round 10
// baseline (speedup 1.0000x reference)
#include <cuda_runtime.h>
#include <math.h>
#include <stdint.h>

#define XD    50
#define LEN   230
#define KF    150
#define KSTEPS 20          // K padded to 160 = 20 x 8
#define NOUT  1380
#define NP    1408
#define BTOT  16384

// conv pipeline geometry
#define CHUNK   8
#define NCHUNK  29                 // 28*8 + 6 = 230
#define BPB     5                  // batches per block
#define BSTRIDE_B 1632             // bytes per batch per stage (8*200 + 32 pad)
#define BSTRIDE_W 408              // floats
#define STAGE_B 8160               // 5 * 1632
#define NSTAGE  4

typedef unsigned long long ull;

// A fragment-major: [mtile(16 rows)][kstep(8 cols)][lane*4+slot]
__device__ __align__(16) float g_flatF[(BTOT / 16) * KSTEPS * 128];
// B fragment-major: [n8tile][kstep][lane*2+slot]
__device__ __align__(16) float g_WF[(NP / 8) * KSTEPS * 64];

// ---------------- helpers ----------------
__device__ __forceinline__ ull pk(float lo, float hi) {
    ull r; asm("mov.b64 %0, {%1, %2};" : "=l"(r) : "f"(lo), "f"(hi)); return r;
}
__device__ __forceinline__ void unpk(ull v, float& lo, float& hi) {
    asm("mov.b64 {%0, %1}, %2;" : "=f"(lo), "=f"(hi) : "l"(v));
}
__device__ __forceinline__ ull fma2(ull a, ull b, ull c) {
    ull d; asm("fma.rn.f32x2 %0, %1, %2, %3;" : "=l"(d) : "l"(a), "l"(b), "l"(c)); return d;
}
__device__ __forceinline__ ull mul2(ull a, ull b) {
    ull d; asm("mul.rn.f32x2 %0, %1, %2;" : "=l"(d) : "l"(a), "l"(b)); return d;
}
__device__ __forceinline__ float tf32r(float x) {
    unsigned u; asm("cvt.rna.tf32.f32 %0, %1;" : "=r"(u) : "f"(x));
    return __uint_as_float(u);
}
__device__ __forceinline__ uint32_t smem_u32(const void* p) {
    uint32_t a;
    asm("{ .reg .u64 t; cvta.to.shared.u64 t, %1; cvt.u32.u64 %0, t; }" : "=r"(a) : "l"(p));
    return a;
}
__device__ __forceinline__ void cp16(uint32_t dst, const void* src) {
    asm volatile("cp.async.cg.shared.global [%0], [%1], 16;" :: "r"(dst), "l"(src) : "memory");
}

// fragment-major index for A element (b, k)
__device__ __forceinline__ int a_idx(int b, int k) {
    int mt = b >> 4, row = b & 15, ks = k >> 3, kc = k & 7;
    int lane = ((row & 7) << 2) | (kc & 3);
    int slot = ((kc >> 2) << 1) | (row >> 3);
    return (mt * KSTEPS + ks) * 128 + lane * 4 + slot;
}

// ---------------------------------------------------------------------------
// Stage 0: w_out [NOUT][KF] -> g_WF fragment-major (tf32-rounded, zero pad)
// ---------------------------------------------------------------------------
__global__ __launch_bounds__(256) void wt_kernel(const float* __restrict__ W)
{
    int i = blockIdx.x * 256 + threadIdx.x;
    if (i >= (NP / 8) * KSTEPS * 64) return;
    int n8 = i / (KSTEPS * 64);
    int r  = i - n8 * (KSTEPS * 64);
    int ks = r >> 6, q = r & 63;
    int lane = q >> 1, slot = q & 1;
    int n = n8 * 8 + (lane >> 2);
    int k = ks * 8 + (lane & 3) + 4 * slot;
    g_WF[i] = (n < NOUT && k < KF) ? tf32r(W[n * KF + k]) : 0.f;
}

// ---------------------------------------------------------------------------
// Stage 1: conv + max via cp.async 4-stage smem pipeline, ring[12] registers.
// Load and compute strictly INTERLEAVED per position: ring[S] = x[p] only
// overwrites x[p-12], which is dead (conv12 at p needs x[p-11..p]).
// Block = 128 threads: 5 batches x 25 channel-pairs. Chunk = 8 positions.
// ---------------------------------------------------------------------------
template<int S0, int P0, int CNT>
__device__ __forceinline__ void compute_chunk(
    ull (&ring)[12], const float* row,
    const ull* __restrict__ wa, const ull* __restrict__ wb, const ull* __restrict__ wc,
    float& m1a, float& m1b, float& m2a, float& m2b, float& m3a, float& m3b)
{
    #pragma unroll
    for (int i = 0; i < CNT; i++) {
        const int S = (S0 + i) % 12;
        ring[S] = *(const ull*)(row + i * XD);   // x[p], p = chunk_base + i
        float x, y;
        if (P0 + i >= 2) {
            ull s = mul2(wa[0], ring[(S + 10) % 12]);
            s = fma2(wa[1], ring[(S + 11) % 12], s);
            s = fma2(wa[2], ring[S], s);
            unpk(s, x, y); m1a = fmaxf(m1a, x); m1b = fmaxf(m1b, y);
        }
        if (P0 + i >= 5) {
            ull s = mul2(wb[0], ring[(S + 7) % 12]);
            #pragma unroll
            for (int j = 1; j < 6; j++) s = fma2(wb[j], ring[(S + 7 + j) % 12], s);
            unpk(s, x, y); m2a = fmaxf(m2a, x); m2b = fmaxf(m2b, y);
        }
        if (P0 + i >= 11) {
            ull s = mul2(wc[0], ring[(S + 1) % 12]);
            #pragma unroll
            for (int j = 1; j < 12; j++) s = fma2(wc[j], ring[(S + 1 + j) % 12], s);
            unpk(s, x, y); m3a = fmaxf(m3a, x); m3b = fmaxf(m3b, y);
        }
    }
}

__global__ __launch_bounds__(128, 6) void conv_max_kernel(
    const float* __restrict__ seq,
    const float* __restrict__ w1, const float* __restrict__ b1,
    const float* __restrict__ w2, const float* __restrict__ b2,
    const float* __restrict__ w3, const float* __restrict__ b3,
    int nbat)
{
    __shared__ __align__(16) char sbuf[NSTAGE * STAGE_B];   // 31.9 KB

    const int tid = threadIdx.x;
    const int b0  = blockIdx.x * BPB;
    const int lb  = tid / 25;
    const int p   = tid - lb * 25;
    const bool active = (tid < 125) && (b0 + lb < nbat);
    const uint32_t sbase = smem_u32(sbuf);
    const int c0 = 2 * p, c1 = 2 * p + 1;

    // prefetch one chunk (100 float4 per batch; last chunk 75)
    auto prefetch = [&](int c) {
        if (c >= NCHUNK) return;
        const int cnt = (c == NCHUNK - 1) ? 75 : 100;
        const uint32_t dbase = sbase + (c & 3) * STAGE_B;
        const char* src0 = (const char*)seq + (size_t)c * (CHUNK * XD * 4);
        #pragma unroll
        for (int r = 0; r < 4; r++) {
            int i = tid + r * 128;
            if (i < 500) {
                int bat = i / 100, ri = i - bat * 100;
                if (b0 + bat < nbat && ri < cnt)
                    cp16(dbase + bat * BSTRIDE_B + ri * 16,
                         src0 + (size_t)(b0 + bat) * (LEN * XD * 4) + ri * 16);
            }
        }
        asm volatile("cp.async.commit_group;" ::: "memory");
    };

    ull wa[3], wb[6], wc[12];
    #pragma unroll
    for (int i = 0; i < 3;  i++) wa[i] = pk(w1[3 * c0 + i],  w1[3 * c1 + i]);
    #pragma unroll
    for (int i = 0; i < 6;  i++) wb[i] = pk(w2[6 * c0 + i],  w2[6 * c1 + i]);
    #pragma unroll
    for (int i = 0; i < 12; i++) wc[i] = pk(w3[12 * c0 + i], w3[12 * c1 + i]);

    ull ring[12];
    float m1a = -INFINITY, m1b = -INFINITY;
    float m2a = -INFINITY, m2b = -INFINITY;
    float m3a = -INFINITY, m3b = -INFINITY;

    prefetch(0); prefetch(1); prefetch(2);

    #define PIPE(c, S0v, P0v, CNTv) \
        asm volatile("cp.async.wait_group 2;" ::: "memory"); \
        __syncthreads(); \
        prefetch((c) + 3); \
        if (active) \
            compute_chunk<S0v, P0v, CNTv>(ring, \
                (const float*)(sbuf + ((c) & 3) * STAGE_B) + lb * BSTRIDE_W + 2 * p, \
                wa, wb, wc, m1a, m1b, m2a, m2b, m3a, m3b);

    PIPE(0, 0, 0, 8)            // positions 0..7  (partial convs)
    PIPE(1, 8, 8, 8)            // positions 8..15 (conv12 from p=11)
    #pragma unroll 1
    for (int c = 2; c < 26; c += 3) {
        PIPE(c,     4, 100, 8)
        PIPE(c + 1, 0, 100, 8)
        PIPE(c + 2, 8, 100, 8)
    }
    PIPE(26, 4, 100, 8)
    PIPE(27, 0, 100, 8)
    PIPE(28, 8, 100, 6)         // positions 224..229
    #undef PIPE

    if (active) {
        const int b = b0 + lb;
        g_flatF[a_idx(b, 3 * c0 + 0)] = tf32r(m1a + b1[c0]);
        g_flatF[a_idx(b, 3 * c0 + 1)] = tf32r(m2a + b2[c0]);
        g_flatF[a_idx(b, 3 * c0 + 2)] = tf32r(m3a + b3[c0]);
        g_flatF[a_idx(b, 3 * c1 + 0)] = tf32r(m1b + b1[c1]);
        g_flatF[a_idx(b, 3 * c1 + 1)] = tf32r(m2b + b2[c1]);
        g_flatF[a_idx(b, 3 * c1 + 2)] = tf32r(m3b + b3[c1]);
        if (p < 5) {
            g_flatF[a_idx(b, KF + 2 * p)]     = 0.f;
            g_flatF[a_idx(b, KF + 2 * p + 1)] = 0.f;
        }
    }
}

// ---------------------------------------------------------------------------
// Stage 2: tf32 mma.sync GEMM, cp.async double-buffered over 4 K-chunks of
// 5 ksteps. CTA 128x128, 8 warps 2x4, warp tile 64x32. 80KB smem -> 2 CTA/SM.
// ---------------------------------------------------------------------------
#define CH_A 1280
#define CH_B 1280
#define BUF_F4 (CH_A + CH_B)
#define SMEM_SZ (2 * BUF_F4 * 16)   // 80KB

__device__ __forceinline__ void mma_tf32_16n8k8(
    float& c0, float& c1, float& c2, float& c3,
    uint32_t a0, uint32_t a1, uint32_t a2, uint32_t a3,
    uint32_t b0, uint32_t b1)
{
    asm volatile(
        "mma.sync.aligned.m16n8k8.row.col.f32.tf32.tf32.f32 "
        "{%0,%1,%2,%3}, {%4,%5,%6,%7}, {%8,%9}, {%0,%1,%2,%3};"
        : "+f"(c0), "+f"(c1), "+f"(c2), "+f"(c3)
        : "r"(a0), "r"(a1), "r"(a2), "r"(a3), "r"(b0), "r"(b1));
}

__global__ __launch_bounds__(256, 2)
void mma_kernel(const float* __restrict__ bias, float* __restrict__ out, int nbat)
{
    extern __shared__ float smem[];
    const uint32_t sb = smem_u32(smem);
    const int tid  = threadIdx.x;
    const int warp = tid >> 5, lane = tid & 31;
    const int wm = warp & 1, wn = warp >> 1;
    const int bm = blockIdx.y * 128, bn = blockIdx.x * 128;
    const int mtg = bm >> 4, ntg = bn >> 3;

    const float4* gA = (const float4*)g_flatF;
    const float4* gB = (const float4*)g_WF;

    auto prefetch = [&](int c, int buf) {
        uint32_t dbase = sb + buf * (BUF_F4 * 16);
        #pragma unroll
        for (int rep = 0; rep < 10; rep++) {
            int i = tid + rep * 256;
            if (i < CH_A) {
                int mt = i / 160, r = i - mt * 160;
                cp16(dbase + i * 16, gA + (size_t)((mtg + mt) * KSTEPS + c * 5) * 32 + r);
            } else {
                int j = i - CH_A;
                int nt = j / 80, r = j - nt * 80;
                cp16(dbase + i * 16, gB + (size_t)((ntg + nt) * KSTEPS + c * 5) * 16 + r);
            }
        }
        asm volatile("cp.async.commit_group;" ::: "memory");
    };

    float acc[4][4][4];
    #pragma unroll
    for (int i = 0; i < 4; i++)
        #pragma unroll
        for (int j = 0; j < 4; j++)
            #pragma unroll
            for (int r = 0; r < 4; r++) acc[i][j][r] = 0.f;

    prefetch(0, 0);
    #pragma unroll
    for (int c = 0; c < 4; c++) {
        if (c < 3) prefetch(c + 1, (c + 1) & 1);
        if (c < 3) asm volatile("cp.async.wait_group 1;" ::: "memory");
        else       asm volatile("cp.async.wait_group 0;" ::: "memory");
        __syncthreads();

        const float* buf = smem + (c & 1) * (BUF_F4 * 4);
        const float* sA = buf;
        const float* sB = buf + CH_A * 4;
        #pragma unroll
        for (int ks = 0; ks < 5; ks++) {
            uint32_t a[4][4], b[4][2];
            #pragma unroll
            for (int mt = 0; mt < 4; mt++) {
                float4 v = *(const float4*)(sA + ((wm * 4 + mt) * 5 + ks) * 128 + lane * 4);
                a[mt][0] = __float_as_uint(v.x); a[mt][1] = __float_as_uint(v.y);
                a[mt][2] = __float_as_uint(v.z); a[mt][3] = __float_as_uint(v.w);
            }
            #pragma unroll
            for (int nt = 0; nt < 4; nt++) {
                float2 v = *(const float2*)(sB + ((wn * 4 + nt) * 5 + ks) * 64 + lane * 2);
                b[nt][0] = __float_as_uint(v.x); b[nt][1] = __float_as_uint(v.y);
            }
            #pragma unroll
            for (int mt = 0; mt < 4; mt++)
                #pragma unroll
                for (int nt = 0; nt < 4; nt++)
                    mma_tf32_16n8k8(acc[mt][nt][0], acc[mt][nt][1],
                                    acc[mt][nt][2], acc[mt][nt][3],
                                    a[mt][0], a[mt][1], a[mt][2], a[mt][3],
                                    b[nt][0], b[nt][1]);
        }
        __syncthreads();
    }

    const int g  = lane >> 2;
    const int tg = lane & 3;
    #pragma unroll
    for (int mt = 0; mt < 4; mt++) {
        int row0 = bm + wm * 64 + mt * 16 + g;
        int row1 = row0 + 8;
        #pragma unroll
        for (int nt = 0; nt < 4; nt++) {
            int col = bn + wn * 32 + nt * 8 + 2 * tg;
            if (col < NOUT) {
                float2 bb = *(const float2*)(bias + col);
                if (row0 < nbat) {
                    float2 v = {acc[mt][nt][0] + bb.x, acc[mt][nt][1] + bb.y};
                    *(float2*)(out + (size_t)row0 * NOUT + col) = v;
                }
                if (row1 < nbat) {
                    float2 v = {acc[mt][nt][2] + bb.x, acc[mt][nt][3] + bb.y};
                    *(float2*)(out + (size_t)row1 * NOUT + col) = v;
                }
            }
        }
    }
}

// ---------------------------------------------------------------------------
extern "C" void kernel_launch(void* const* d_in, const int* in_sizes, int n_in,
                              void* d_out, int out_size)
{
    const float* seq   = (const float*)d_in[0];
    const float* w1    = (const float*)d_in[1];
    const float* b1    = (const float*)d_in[2];
    const float* w2    = (const float*)d_in[3];
    const float* b2    = (const float*)d_in[4];
    const float* w3    = (const float*)d_in[5];
    const float* b3    = (const float*)d_in[6];
    const float* w_out = (const float*)d_in[7];
    const float* b_out = (const float*)d_in[8];
    float* out = (float*)d_out;

    const int B = in_sizes[0] / (LEN * XD);

    static int smem_set = 0;
    if (!smem_set) {
        cudaFuncSetAttribute(mma_kernel, cudaFuncAttributeMaxDynamicSharedMemorySize, SMEM_SZ);
        smem_set = 1;
    }

    conv_max_kernel<<<(B + BPB - 1) / BPB, 128>>>(seq, w1, b1, w2, b2, w3, b3, B);
    wt_kernel<<<((NP / 8) * KSTEPS * 64 + 255) / 256, 256>>>(w_out);

    dim3 grid(NP / 128, (B + 127) / 128);
    mma_kernel<<<grid, 256, SMEM_SZ>>>(b_out, out, B);
}

// round 11
// speedup vs baseline: 1.3782x; 1.3782x over previous
#include <cuda_runtime.h>
#include <math.h>
#include <stdint.h>

#define XD    50
#define LEN   230
#define KF    150
#define KSTEPS 20          // K padded to 160 = 20 x 8
#define NOUT  1380
#define NP    1408
#define BTOT  16384

// conv pipeline geometry
#define CHUNK   8
#define NCHUNK  29                 // 28*8 + 6 = 230
#define BPB     5                  // batches per block
#define BSTRIDE_B 1632             // bytes per batch per stage (8*200 + 32 pad)
#define BSTRIDE_W 408              // floats
#define STAGE_B 8160               // 5 * 1632
#define NSTAGE  4

typedef unsigned long long ull;

// A fragment-major: [mtile(16 rows)][kstep(8 cols)][lane*4+slot]
__device__ __align__(16) float g_flatF[(BTOT / 16) * KSTEPS * 128];
// B fragment-major: [n8tile][kstep][lane*2+slot]
__device__ __align__(16) float g_WF[(NP / 8) * KSTEPS * 64];

// ---------------- helpers ----------------
__device__ __forceinline__ ull pk(float lo, float hi) {
    ull r; asm("mov.b64 %0, {%1, %2};" : "=l"(r) : "f"(lo), "f"(hi)); return r;
}
__device__ __forceinline__ void unpk(ull v, float& lo, float& hi) {
    asm("mov.b64 {%0, %1}, %2;" : "=f"(lo), "=f"(hi) : "l"(v));
}
__device__ __forceinline__ ull fma2(ull a, ull b, ull c) {
    ull d; asm("fma.rn.f32x2 %0, %1, %2, %3;" : "=l"(d) : "l"(a), "l"(b), "l"(c)); return d;
}
__device__ __forceinline__ ull mul2(ull a, ull b) {
    ull d; asm("mul.rn.f32x2 %0, %1, %2;" : "=l"(d) : "l"(a), "l"(b)); return d;
}
__device__ __forceinline__ float tf32r(float x) {
    unsigned u; asm("cvt.rna.tf32.f32 %0, %1;" : "=r"(u) : "f"(x));
    return __uint_as_float(u);
}
__device__ __forceinline__ uint32_t smem_u32(const void* p) {
    uint32_t a;
    asm("{ .reg .u64 t; cvta.to.shared.u64 t, %1; cvt.u32.u64 %0, t; }" : "=r"(a) : "l"(p));
    return a;
}
__device__ __forceinline__ void cp16(uint32_t dst, const void* src) {
    asm volatile("cp.async.cg.shared.global [%0], [%1], 16;" :: "r"(dst), "l"(src) : "memory");
}

// fragment-major index for A element (b, k)
__device__ __forceinline__ int a_idx(int b, int k) {
    int mt = b >> 4, row = b & 15, ks = k >> 3, kc = k & 7;
    int lane = ((row & 7) << 2) | (kc & 3);
    int slot = ((kc >> 2) << 1) | (row >> 3);
    return (mt * KSTEPS + ks) * 128 + lane * 4 + slot;
}

// ---------------------------------------------------------------------------
// Stage 0: w_out [NOUT][KF] -> g_WF fragment-major (tf32-rounded, zero pad)
// ---------------------------------------------------------------------------
__global__ __launch_bounds__(256) void wt_kernel(const float* __restrict__ W)
{
    int i = blockIdx.x * 256 + threadIdx.x;
    if (i >= (NP / 8) * KSTEPS * 64) return;
    int n8 = i / (KSTEPS * 64);
    int r  = i - n8 * (KSTEPS * 64);
    int ks = r >> 6, q = r & 63;
    int lane = q >> 1, slot = q & 1;
    int n = n8 * 8 + (lane >> 2);
    int k = ks * 8 + (lane & 3) + 4 * slot;
    g_WF[i] = (n < NOUT && k < KF) ? tf32r(W[n * KF + k]) : 0.f;
}

// ---------------------------------------------------------------------------
// Stage 1: conv + max via cp.async 4-stage smem pipeline, ring[16] registers
// with LEAD-3 refill: at step i load position base+i+3 (slot (S0+i+3)%16),
// then compute position base+i. Load of x[q] overwrites x[q-16], last used
// at compute q-16+11 = two steps earlier -> safe, and the LDS leads its
// consumer by 3 positions (~120 issue slots > 29-cycle LDS latency).
// Block = 128 threads: 5 batches x 25 channel-pairs. Chunk = 8 positions.
// ---------------------------------------------------------------------------
template<int S0, int P0, int CNT, int L0, int L1>
__device__ __forceinline__ void chunk_step(
    ull (&ring)[16], const float* row_cur, const float* row_next,
    const ull* __restrict__ wa, const ull* __restrict__ wb, const ull* __restrict__ wc,
    float& m1a, float& m1b, float& m2a, float& m2b, float& m3a, float& m3b)
{
    constexpr int STEPS = (CNT > L1 - L0) ? CNT : (L1 - L0);
    #pragma unroll
    for (int i = 0; i < STEPS; i++) {
        const int LP = i + L0;
        if (LP < L1) {
            const int S = (S0 + LP) % 16;
            ring[S] = (LP < CHUNK) ? *(const ull*)(row_cur + LP * XD)
                                   : *(const ull*)(row_next + (LP - CHUNK) * XD);
        }
        if (i < CNT) {
            const int S = (S0 + i) % 16;
            float x, y;
            if (P0 + i >= 2) {
                ull s = mul2(wa[0], ring[(S + 14) % 16]);
                s = fma2(wa[1], ring[(S + 15) % 16], s);
                s = fma2(wa[2], ring[S], s);
                unpk(s, x, y); m1a = fmaxf(m1a, x); m1b = fmaxf(m1b, y);
            }
            if (P0 + i >= 5) {
                ull s = mul2(wb[0], ring[(S + 11) % 16]);
                #pragma unroll
                for (int j = 1; j < 6; j++) s = fma2(wb[j], ring[(S + 11 + j) % 16], s);
                unpk(s, x, y); m2a = fmaxf(m2a, x); m2b = fmaxf(m2b, y);
            }
            if (P0 + i >= 11) {
                ull s = mul2(wc[0], ring[(S + 5) % 16]);
                #pragma unroll
                for (int j = 1; j < 12; j++) s = fma2(wc[j], ring[(S + 5 + j) % 16], s);
                unpk(s, x, y); m3a = fmaxf(m3a, x); m3b = fmaxf(m3b, y);
            }
        }
    }
}

__global__ __launch_bounds__(128, 5) void conv_max_kernel(
    const float* __restrict__ seq,
    const float* __restrict__ w1, const float* __restrict__ b1,
    const float* __restrict__ w2, const float* __restrict__ b2,
    const float* __restrict__ w3, const float* __restrict__ b3,
    int nbat)
{
    __shared__ __align__(16) char sbuf[NSTAGE * STAGE_B];   // 31.9 KB

    const int tid = threadIdx.x;
    const int b0  = blockIdx.x * BPB;
    const int lb  = tid / 25;
    const int p   = tid - lb * 25;
    const bool active = (tid < 125) && (b0 + lb < nbat);
    const uint32_t sbase = smem_u32(sbuf);
    const int c0 = 2 * p, c1 = 2 * p + 1;

    // prefetch one chunk (100 float4 per batch; last chunk 75). ALWAYS commits
    // (even past NCHUNK) so wait_group counts stay aligned with chunk index.
    auto prefetch = [&](int c) {
        if (c < NCHUNK) {
            const int cnt = (c == NCHUNK - 1) ? 75 : 100;
            const uint32_t dbase = sbase + (c & 3) * STAGE_B;
            const char* src0 = (const char*)seq + (size_t)c * (CHUNK * XD * 4);
            #pragma unroll
            for (int r = 0; r < 4; r++) {
                int i = tid + r * 128;
                if (i < 500) {
                    int bat = i / 100, ri = i - bat * 100;
                    if (b0 + bat < nbat && ri < cnt)
                        cp16(dbase + bat * BSTRIDE_B + ri * 16,
                             src0 + (size_t)(b0 + bat) * (LEN * XD * 4) + ri * 16);
                }
            }
        }
        asm volatile("cp.async.commit_group;" ::: "memory");
    };

    ull wa[3], wb[6], wc[12];
    #pragma unroll
    for (int i = 0; i < 3;  i++) wa[i] = pk(w1[3 * c0 + i],  w1[3 * c1 + i]);
    #pragma unroll
    for (int i = 0; i < 6;  i++) wb[i] = pk(w2[6 * c0 + i],  w2[6 * c1 + i]);
    #pragma unroll
    for (int i = 0; i < 12; i++) wc[i] = pk(w3[12 * c0 + i], w3[12 * c1 + i]);

    ull ring[16];
    float m1a = -INFINITY, m1b = -INFINITY;
    float m2a = -INFINITY, m2b = -INFINITY;
    float m3a = -INFINITY, m3b = -INFINITY;

    prefetch(0); prefetch(1); prefetch(2);

    const float* rowbase = (const float*)sbuf + lb * BSTRIDE_W + 2 * p;
    #define ROW(c) (rowbase + ((c) & 3) * (STAGE_B / 4))

    // wait_group 1 -> stages c and c+1 complete (chunk c reads both)
    #define PIPE(c, S0v, P0v, CNTv, L0v, L1v) \
        asm volatile("cp.async.wait_group 1;" ::: "memory"); \
        __syncthreads(); \
        prefetch((c) + 3); \
        if (active) \
            chunk_step<S0v, P0v, CNTv, L0v, L1v>(ring, ROW(c), ROW((c) + 1), \
                wa, wb, wc, m1a, m1b, m2a, m2b, m3a, m3b);

    PIPE(0, 0, 0, 8, 0, 11)           // computes 0..7, loads 0..10
    PIPE(1, 8, 8, 8, 3, 11)           // computes 8..15, loads 11..18
    #pragma unroll 1
    for (int c = 2; c < 28; c += 2) {
        PIPE(c,     0, 100, 8, 3, 11)
        PIPE(c + 1, 8, 100, 8, 3, 11)
    }
    PIPE(28, 0, 100, 6, 3, 6)         // computes 224..229, loads 227..229
    #undef PIPE
    #undef ROW

    if (active) {
        const int b = b0 + lb;
        g_flatF[a_idx(b, 3 * c0 + 0)] = tf32r(m1a + b1[c0]);
        g_flatF[a_idx(b, 3 * c0 + 1)] = tf32r(m2a + b2[c0]);
        g_flatF[a_idx(b, 3 * c0 + 2)] = tf32r(m3a + b3[c0]);
        g_flatF[a_idx(b, 3 * c1 + 0)] = tf32r(m1b + b1[c1]);
        g_flatF[a_idx(b, 3 * c1 + 1)] = tf32r(m2b + b2[c1]);
        g_flatF[a_idx(b, 3 * c1 + 2)] = tf32r(m3b + b3[c1]);
        if (p < 5) {
            g_flatF[a_idx(b, KF + 2 * p)]     = 0.f;
            g_flatF[a_idx(b, KF + 2 * p + 1)] = 0.f;
        }
    }
}

// ---------------------------------------------------------------------------
// Stage 2: tf32 mma.sync GEMM, cp.async double-buffered over 4 K-chunks of
// 5 ksteps. CTA 128x128, 8 warps 2x4, warp tile 64x32. 80KB smem -> 2 CTA/SM.
// ---------------------------------------------------------------------------
#define CH_A 1280
#define CH_B 1280
#define BUF_F4 (CH_A + CH_B)
#define SMEM_SZ (2 * BUF_F4 * 16)   // 80KB

__device__ __forceinline__ void mma_tf32_16n8k8(
    float& c0, float& c1, float& c2, float& c3,
    uint32_t a0, uint32_t a1, uint32_t a2, uint32_t a3,
    uint32_t b0, uint32_t b1)
{
    asm volatile(
        "mma.sync.aligned.m16n8k8.row.col.f32.tf32.tf32.f32 "
        "{%0,%1,%2,%3}, {%4,%5,%6,%7}, {%8,%9}, {%0,%1,%2,%3};"
        : "+f"(c0), "+f"(c1), "+f"(c2), "+f"(c3)
        : "r"(a0), "r"(a1), "r"(a2), "r"(a3), "r"(b0), "r"(b1));
}

__global__ __launch_bounds__(256, 2)
void mma_kernel(const float* __restrict__ bias, float* __restrict__ out, int nbat)
{
    extern __shared__ float smem[];
    const uint32_t sb = smem_u32(smem);
    const int tid  = threadIdx.x;
    const int warp = tid >> 5, lane = tid & 31;
    const int wm = warp & 1, wn = warp >> 1;
    const int bm = blockIdx.y * 128, bn = blockIdx.x * 128;
    const int mtg = bm >> 4, ntg = bn >> 3;

    const float4* gA = (const float4*)g_flatF;
    const float4* gB = (const float4*)g_WF;

    auto prefetch = [&](int c, int buf) {
        uint32_t dbase = sb + buf * (BUF_F4 * 16);
        #pragma unroll
        for (int rep = 0; rep < 10; rep++) {
            int i = tid + rep * 256;
            if (i < CH_A) {
                int mt = i / 160, r = i - mt * 160;
                cp16(dbase + i * 16, gA + (size_t)((mtg + mt) * KSTEPS + c * 5) * 32 + r);
            } else {
                int j = i - CH_A;
                int nt = j / 80, r = j - nt * 80;
                cp16(dbase + i * 16, gB + (size_t)((ntg + nt) * KSTEPS + c * 5) * 16 + r);
            }
        }
        asm volatile("cp.async.commit_group;" ::: "memory");
    };

    float acc[4][4][4];
    #pragma unroll
    for (int i = 0; i < 4; i++)
        #pragma unroll
        for (int j = 0; j < 4; j++)
            #pragma unroll
            for (int r = 0; r < 4; r++) acc[i][j][r] = 0.f;

    prefetch(0, 0);
    #pragma unroll
    for (int c = 0; c < 4; c++) {
        if (c < 3) prefetch(c + 1, (c + 1) & 1);
        if (c < 3) asm volatile("cp.async.wait_group 1;" ::: "memory");
        else       asm volatile("cp.async.wait_group 0;" ::: "memory");
        __syncthreads();

        const float* buf = smem + (c & 1) * (BUF_F4 * 4);
        const float* sA = buf;
        const float* sB = buf + CH_A * 4;
        #pragma unroll
        for (int ks = 0; ks < 5; ks++) {
            uint32_t a[4][4], b[4][2];
            #pragma unroll
            for (int mt = 0; mt < 4; mt++) {
                float4 v = *(const float4*)(sA + ((wm * 4 + mt) * 5 + ks) * 128 + lane * 4);
                a[mt][0] = __float_as_uint(v.x); a[mt][1] = __float_as_uint(v.y);
                a[mt][2] = __float_as_uint(v.z); a[mt][3] = __float_as_uint(v.w);
            }
            #pragma unroll
            for (int nt = 0; nt < 4; nt++) {
                float2 v = *(const float2*)(sB + ((wn * 4 + nt) * 5 + ks) * 64 + lane * 2);
                b[nt][0] = __float_as_uint(v.x); b[nt][1] = __float_as_uint(v.y);
            }
            #pragma unroll
            for (int mt = 0; mt < 4; mt++)
                #pragma unroll
                for (int nt = 0; nt < 4; nt++)
                    mma_tf32_16n8k8(acc[mt][nt][0], acc[mt][nt][1],
                                    acc[mt][nt][2], acc[mt][nt][3],
                                    a[mt][0], a[mt][1], a[mt][2], a[mt][3],
                                    b[nt][0], b[nt][1]);
        }
        __syncthreads();
    }

    const int g  = lane >> 2;
    const int tg = lane & 3;
    #pragma unroll
    for (int mt = 0; mt < 4; mt++) {
        int row0 = bm + wm * 64 + mt * 16 + g;
        int row1 = row0 + 8;
        #pragma unroll
        for (int nt = 0; nt < 4; nt++) {
            int col = bn + wn * 32 + nt * 8 + 2 * tg;
            if (col < NOUT) {
                float2 bb = *(const float2*)(bias + col);
                if (row0 < nbat) {
                    float2 v = {acc[mt][nt][0] + bb.x, acc[mt][nt][1] + bb.y};
                    *(float2*)(out + (size_t)row0 * NOUT + col) = v;
                }
                if (row1 < nbat) {
                    float2 v = {acc[mt][nt][2] + bb.x, acc[mt][nt][3] + bb.y};
                    *(float2*)(out + (size_t)row1 * NOUT + col) = v;
                }
            }
        }
    }
}

// ---------------------------------------------------------------------------
extern "C" void kernel_launch(void* const* d_in, const int* in_sizes, int n_in,
                              void* d_out, int out_size)
{
    const float* seq   = (const float*)d_in[0];
    const float* w1    = (const float*)d_in[1];
    const float* b1    = (const float*)d_in[2];
    const float* w2    = (const float*)d_in[3];
    const float* b2    = (const float*)d_in[4];
    const float* w3    = (const float*)d_in[5];
    const float* b3    = (const float*)d_in[6];
    const float* w_out = (const float*)d_in[7];
    const float* b_out = (const float*)d_in[8];
    float* out = (float*)d_out;

    const int B = in_sizes[0] / (LEN * XD);

    static int smem_set = 0;
    if (!smem_set) {
        cudaFuncSetAttribute(mma_kernel, cudaFuncAttributeMaxDynamicSharedMemorySize, SMEM_SZ);
        smem_set = 1;
    }

    conv_max_kernel<<<(B + BPB - 1) / BPB, 128>>>(seq, w1, b1, w2, b2, w3, b3, B);
    wt_kernel<<<((NP / 8) * KSTEPS * 64 + 255) / 256, 256>>>(w_out);

    dim3 grid(NP / 128, (B + 127) / 128);
    mma_kernel<<<grid, 256, SMEM_SZ>>>(b_out, out, B);
}